// round 7
// baseline (speedup 1.0000x reference)
#include <cuda_runtime.h>
#include <cstdint>

// GatingFeatureExtractor: p[B, E=8, C=1000] fp32 -> feats[B, E*C + 3E + 5] fp32.
// One CTA per batch row:
//   A:  cp.async gmem row -> smem (32KB) [issued first]
//   D:  independent gmem->gmem copy with shift-corrected STG.128 (reads are
//       L2-hot behind the cp.async fills); runs BEFORE the cp.async wait.
//   B:  warp w = expert w: top2/argmax only (float4 LDS, no MUFU)
//   C:  thread t<250 owns classes 4t..4t+3: plogp[8] + prefix-KL cross +
//       mixture entropy + variance from conflict-free LDS.128
//   F:  thread 0 finalizes the 29 stat columns.

#define EPS_F 1e-8f

constexpr int E = 8;
constexpr int C = 1000;
constexpr int C4 = C / 4;                  // 250
constexpr int EC = E * C;                  // 8000
constexpr int OUTW = EC + 3 * E + 5;       // 8029
constexpr int NT = 256;
constexpr int NW = NT / 32;

__device__ __forceinline__ void cp_async16(uint32_t saddr, const void* gptr) {
    asm volatile("cp.async.cg.shared.global [%0], [%1], 16;\n" ::"r"(saddr), "l"(gptr));
}

__global__ __launch_bounds__(NT, 6)
void gating_feats_kernel(const float* __restrict__ pin, float* __restrict__ out)
{
    __shared__ __align__(16) float sp[EC];
    __shared__ float sh_mx1[E], sh_mx2[E];
    __shared__ int   sh_ix1[E];
    __shared__ float sh_red[NW][11];               // plogp[8], cross, mixent, var

    const int b    = blockIdx.x;
    const int tid  = threadIdx.x;
    const int wid  = tid >> 5;
    const int lane = tid & 31;

    const float* __restrict__ pr = pin + (size_t)b * EC;
    float* __restrict__ orow = out + (size_t)b * OUTW;
    // (b*OUTW)%4 == b%4 since OUTW%4==1; dst float4 frame starts at h.
    const int h = (4 - (b & 3)) & 3;

    // ---------------- Phase A: stage row into smem via cp.async ----------------
    if (tid < C4) {                                 // 250 threads, 8 x 16B each
        uint32_t sbase = (uint32_t)__cvta_generic_to_shared(sp) + 16u * (uint32_t)tid;
#pragma unroll
        for (int e = 0; e < E; e++)
            cp_async16(sbase + (uint32_t)(e * C * 4), pr + e * C + 4 * tid);
    }
    asm volatile("cp.async.commit_group;\n" ::: "memory");

    // -------- Phase D: gmem->gmem shifted copy (overlaps cp.async wait) --------
    {
        const float4* __restrict__ pr4 = reinterpret_cast<const float4*>(pr);
        if (h == 0) {
            float4* __restrict__ dst4 = reinterpret_cast<float4*>(orow);
#pragma unroll
            for (int k = 0; k < 8; k++) {
                int j = tid + NT * k;
                if (j < EC / 4) dst4[j] = pr4[j];
            }
        } else {
            const int nvec = (EC - h) >> 2;        // 1999
            float4* __restrict__ dst4 = reinterpret_cast<float4*>(orow + h);
#pragma unroll
            for (int k = 0; k < 8; k++) {
                int j = tid + NT * k;
                if (j < nvec) {
                    float4 v = pr4[j];
                    float4 w = pr4[j + 1];          // in-bounds: j+1 <= 1999
                    float4 o;
                    if (h == 1)      { o.x = v.y; o.y = v.z; o.z = v.w; o.w = w.x; }
                    else if (h == 2) { o.x = v.z; o.y = v.w; o.z = w.x; o.w = w.y; }
                    else             { o.x = v.w; o.y = w.x; o.z = w.y; o.w = w.z; }
                    dst4[j] = o;
                }
            }
            if (tid < h)     orow[tid] = pr[tid];                          // head
            if (tid < 4 - h) orow[h + 4 * nvec + tid] = pr[h + 4 * nvec + tid]; // tail
        }
    }

    asm volatile("cp.async.wait_group 0;\n" ::: "memory");
    __syncthreads();

    // -------- Phase B: per-expert top2/argmax (warp = expert), no MUFU --------
    {
        const float4* __restrict__ row4 = reinterpret_cast<const float4*>(sp + wid * C);
        float m1 = -1.f, m2 = -1.f;
        int i1 = 0;
#pragma unroll
        for (int k = 0; k < 8; k++) {
            int idx = lane + 32 * k;
            if (idx < C4) {
                float4 v = row4[idx];
                float vv[4] = {v.x, v.y, v.z, v.w};
#pragma unroll
                for (int i = 0; i < 4; i++) {
                    float f = vv[i];
                    if (f > m1) { m2 = m1; m1 = f; i1 = 4 * idx + i; }
                    else        { m2 = fmaxf(m2, f); }
                }
            }
        }
#pragma unroll
        for (int off = 16; off; off >>= 1) {
            float o1 = __shfl_xor_sync(0xffffffffu, m1, off);
            float o2 = __shfl_xor_sync(0xffffffffu, m2, off);
            int   oi = __shfl_xor_sync(0xffffffffu, i1, off);
            if (o1 > m1 || (o1 == m1 && oi < i1)) {
                m2 = fmaxf(m1, o2); m1 = o1; i1 = oi;
            } else {
                m2 = fmaxf(m2, o1);
            }
        }
        if (lane == 0) { sh_mx1[wid] = m1; sh_mx2[wid] = m2; sh_ix1[wid] = i1; }
    }

    // ---------------- Phase C: single-pass cross-expert + plogp ----------------
    {
        float plogp[E];
#pragma unroll
        for (int e = 0; e < E; e++) plogp[e] = 0.f;
        float s_cross = 0.f, s_mixent = 0.f, s_var = 0.f;

        if (tid < C4) {                             // thread owns classes 4t..4t+3
            float pre[4] = {0.f, 0.f, 0.f, 0.f};
            float ssq[4] = {0.f, 0.f, 0.f, 0.f};
#pragma unroll
            for (int e = 0; e < E; e++) {
                float4 v = reinterpret_cast<const float4*>(sp + e * C)[tid];
                float vv[4] = {v.x, v.y, v.z, v.w};
                float pe = 0.f;
#pragma unroll
                for (int i = 0; i < 4; i++) {
                    float f = vv[i];
                    float lg = __logf(f + EPS_F);
                    pe = fmaf(f, lg, pe);
                    s_cross = fmaf(lg, pre[i], s_cross);  // sum_{i<j} p_i * logp_j
                    pre[i] += f;
                    ssq[i] = fmaf(f, f, ssq[i]);
                }
                plogp[e] = pe;
            }
#pragma unroll
            for (int i = 0; i < 4; i++) {
                float m = pre[i] * (1.0f / E);      // pre[] = full expert sum
                s_mixent = fmaf(-m, __logf(m + EPS_F), s_mixent);
                s_var = fmaf(ssq[i] - (float)E * m * m, 1.0f / (float)(E - 1), s_var);
            }
        }
        float r[11];
#pragma unroll
        for (int e = 0; e < E; e++) r[e] = plogp[e];
        r[8] = s_cross; r[9] = s_mixent; r[10] = s_var;
#pragma unroll
        for (int off = 16; off; off >>= 1)
#pragma unroll
            for (int k = 0; k < 11; k++)
                r[k] += __shfl_xor_sync(0xffffffffu, r[k], off);
        if (lane == 0)
#pragma unroll
            for (int k = 0; k < 11; k++) sh_red[wid][k] = r[k];
    }

    __syncthreads();

    // ---------------- Finalize: 29 stat columns ----------------
    if (tid == 0) {
        float acc[11];
#pragma unroll
        for (int k = 0; k < 11; k++) acc[k] = 0.f;
        for (int w = 0; w < NW; w++)
#pragma unroll
            for (int k = 0; k < 11; k++) acc[k] += sh_red[w][k];

        float sum_pl = 0.f, wsum = 0.f;
        int args[E];
#pragma unroll
        for (int e = 0; e < E; e++) {
            float pl = acc[e];
            orow[EC + e]         = -pl;                      // expert_entropy
            orow[EC + E + e]     = sh_mx1[e];                // expert_confidence
            orow[EC + 2 * E + e] = sh_mx1[e] - sh_mx2[e];    // expert_margin
            sum_pl += pl;
            wsum = fmaf(pl, (float)(E - 1 - e), wsum);
            args[e] = sh_ix1[e];
        }

        // disagreement: sort 8 argmax indices, count unique
        for (int i = 1; i < E; i++) {
            int key = args[i]; int j = i - 1;
            while (j >= 0 && args[j] > key) { args[j + 1] = args[j]; j--; }
            args[j + 1] = key;
        }
        int nuniq = 1;
        for (int i = 1; i < E; i++) nuniq += (args[i] != args[i - 1]) ? 1 : 0;

        const int n_pairs = E * (E - 1) / 2;
        orow[EC + 3 * E + 0] = (float)(nuniq - 1) / (float)(E - 1);  // disagreement_ratio
        orow[EC + 3 * E + 1] = (wsum - acc[8]) / (float)n_pairs;     // mean_pairwise_kl
        orow[EC + 3 * E + 2] = acc[9];                               // mixture_entropy
        orow[EC + 3 * E + 3] = acc[10] / (float)C;                   // post_var
        orow[EC + 3 * E + 4] = acc[9] + sum_pl / (float)E;           // mutual_info
    }
}

extern "C" void kernel_launch(void* const* d_in, const int* in_sizes, int n_in,
                              void* d_out, int out_size)
{
    const float* p = (const float*)d_in[0];
    float* out = (float*)d_out;
    const int B = in_sizes[0] / EC;    // 8192 for this problem's shapes
    gating_feats_kernel<<<B, NT>>>(p, out);
}

// round 8
// speedup vs baseline: 1.1804x; 1.1804x over previous
#include <cuda_runtime.h>
#include <cstdint>

// GatingFeatureExtractor: p[B, E=8, C=1000] fp32 -> feats[B, E*C + 3E + 5] fp32.
// One CTA per batch row, warp-pipelined:
//   A': warp w cp.asyncs ONLY expert w's row (4KB) to smem, waits its own
//       group (per-thread cp.async state), then immediately runs
//   B:  warp w = expert w: top2/argmax (float4 LDS, no MUFU)
//   __syncthreads (all experts staged)
//   D:  shift-corrected aligned copy smem -> out (stores start draining early)
//   C:  thread t<250 owns classes 4t..4t+3: plogp[8] + prefix-KL cross +
//       mixture entropy + variance (conflict-free LDS.128)
//   F:  thread 0 finalizes the 29 stat columns.

#define EPS_F 1e-8f

constexpr int E = 8;
constexpr int C = 1000;
constexpr int C4 = C / 4;                  // 250
constexpr int EC = E * C;                  // 8000
constexpr int OUTW = EC + 3 * E + 5;       // 8029
constexpr int NT = 256;
constexpr int NW = NT / 32;                // 8 == E

__device__ __forceinline__ void cp_async16(uint32_t saddr, const void* gptr) {
    asm volatile("cp.async.cg.shared.global [%0], [%1], 16;\n" ::"r"(saddr), "l"(gptr));
}

__global__ __launch_bounds__(NT, 6)
void gating_feats_kernel(const float* __restrict__ pin, float* __restrict__ out)
{
    __shared__ __align__(16) float sp[EC + 4];     // +4 pad: Phase D overlap read
    __shared__ float sh_mx1[E], sh_mx2[E];
    __shared__ int   sh_ix1[E];
    __shared__ float sh_red[NW][11];               // plogp[8], cross, mixent, var

    const int b    = blockIdx.x;
    const int tid  = threadIdx.x;
    const int wid  = tid >> 5;                     // warp == expert
    const int lane = tid & 31;

    const float* __restrict__ pr = pin + (size_t)b * EC;
    float* __restrict__ orow = out + (size_t)b * OUTW;
    // (b*OUTW)%4 == b%4 since OUTW%4==1; dst float4 frame starts at h.
    const int h = (4 - (b & 3)) & 3;

    // ---- Phase A': warp w stages expert w's row (own cp.async group) ----
    {
        uint32_t sdst = (uint32_t)__cvta_generic_to_shared(sp + wid * C);
        const float* gsrc = pr + wid * C;
#pragma unroll
        for (int k = 0; k < 8; k++) {
            int idx = lane + 32 * k;
            if (idx < C4) cp_async16(sdst + 16u * (uint32_t)idx, gsrc + 4 * idx);
        }
        asm volatile("cp.async.commit_group;\n" ::: "memory");
        asm volatile("cp.async.wait_group 0;\n" ::: "memory");
        __syncwarp();
    }

    // ---- Phase B: per-expert top2/argmax (warp = expert), no MUFU ----
    {
        const float4* __restrict__ row4 = reinterpret_cast<const float4*>(sp + wid * C);
        float m1 = -1.f, m2 = -1.f;
        int i1 = 0;
#pragma unroll
        for (int k = 0; k < 8; k++) {
            int idx = lane + 32 * k;
            if (idx < C4) {
                float4 v = row4[idx];
                float vv[4] = {v.x, v.y, v.z, v.w};
#pragma unroll
                for (int i = 0; i < 4; i++) {
                    float f = vv[i];
                    if (f > m1) { m2 = m1; m1 = f; i1 = 4 * idx + i; }
                    else        { m2 = fmaxf(m2, f); }
                }
            }
        }
#pragma unroll
        for (int off = 16; off; off >>= 1) {
            float o1 = __shfl_xor_sync(0xffffffffu, m1, off);
            float o2 = __shfl_xor_sync(0xffffffffu, m2, off);
            int   oi = __shfl_xor_sync(0xffffffffu, i1, off);
            if (o1 > m1 || (o1 == m1 && oi < i1)) {
                m2 = fmaxf(m1, o2); m1 = o1; i1 = oi;
            } else {
                m2 = fmaxf(m2, o1);
            }
        }
        if (lane == 0) { sh_mx1[wid] = m1; sh_mx2[wid] = m2; sh_ix1[wid] = i1; }
    }

    __syncthreads();   // all experts staged + B results posted

    // ---- Phase D: copy smem -> out, shift-corrected aligned STG.128 ----
    {
        const float4* __restrict__ sp4 = reinterpret_cast<const float4*>(sp);
        if (h == 0) {
            float4* __restrict__ dst4 = reinterpret_cast<float4*>(orow);
#pragma unroll
            for (int k = 0; k < 8; k++) {
                int j = tid + NT * k;
                if (j < EC / 4) dst4[j] = sp4[j];
            }
        } else {
            const int nvec = (EC - h) >> 2;        // 1999
            float4* __restrict__ dst4 = reinterpret_cast<float4*>(orow + h);
#pragma unroll
            for (int k = 0; k < 8; k++) {
                int j = tid + NT * k;
                if (j < nvec) {
                    float4 v = sp4[j];
                    float4 w = sp4[j + 1];          // padded overlap read
                    float4 o;
                    if (h == 1)      { o.x = v.y; o.y = v.z; o.z = v.w; o.w = w.x; }
                    else if (h == 2) { o.x = v.z; o.y = v.w; o.z = w.x; o.w = w.y; }
                    else             { o.x = v.w; o.y = w.x; o.z = w.y; o.w = w.z; }
                    dst4[j] = o;
                }
            }
            if (tid < h)     orow[tid] = sp[tid];                          // head
            if (tid < 4 - h) orow[h + 4 * nvec + tid] = sp[h + 4 * nvec + tid]; // tail
        }
    }

    // ---- Phase C: single-pass cross-expert stats + plogp ----
    {
        float plogp[E];
#pragma unroll
        for (int e = 0; e < E; e++) plogp[e] = 0.f;
        float s_cross = 0.f, s_mixent = 0.f, s_var = 0.f;

        if (tid < C4) {                             // thread owns classes 4t..4t+3
            float pre[4] = {0.f, 0.f, 0.f, 0.f};
            float ssq[4] = {0.f, 0.f, 0.f, 0.f};
#pragma unroll
            for (int e = 0; e < E; e++) {
                float4 v = reinterpret_cast<const float4*>(sp + e * C)[tid];
                float vv[4] = {v.x, v.y, v.z, v.w};
                float pe = 0.f;
#pragma unroll
                for (int i = 0; i < 4; i++) {
                    float f = vv[i];
                    float lg = __logf(f + EPS_F);
                    pe = fmaf(f, lg, pe);
                    s_cross = fmaf(lg, pre[i], s_cross);  // sum_{i<j} p_i * logp_j
                    pre[i] += f;
                    ssq[i] = fmaf(f, f, ssq[i]);
                }
                plogp[e] = pe;
            }
#pragma unroll
            for (int i = 0; i < 4; i++) {
                float m = pre[i] * (1.0f / E);      // pre[] = full expert sum
                s_mixent = fmaf(-m, __logf(m + EPS_F), s_mixent);
                s_var = fmaf(ssq[i] - (float)E * m * m, 1.0f / (float)(E - 1), s_var);
            }
        }
        float r[11];
#pragma unroll
        for (int e = 0; e < E; e++) r[e] = plogp[e];
        r[8] = s_cross; r[9] = s_mixent; r[10] = s_var;
#pragma unroll
        for (int off = 16; off; off >>= 1)
#pragma unroll
            for (int k = 0; k < 11; k++)
                r[k] += __shfl_xor_sync(0xffffffffu, r[k], off);
        if (lane == 0)
#pragma unroll
            for (int k = 0; k < 11; k++) sh_red[wid][k] = r[k];
    }

    __syncthreads();

    // ---- Finalize: 29 stat columns ----
    if (tid == 0) {
        float acc[11];
#pragma unroll
        for (int k = 0; k < 11; k++) acc[k] = 0.f;
        for (int w = 0; w < NW; w++)
#pragma unroll
            for (int k = 0; k < 11; k++) acc[k] += sh_red[w][k];

        float sum_pl = 0.f, wsum = 0.f;
        int args[E];
#pragma unroll
        for (int e = 0; e < E; e++) {
            float pl = acc[e];
            orow[EC + e]         = -pl;                      // expert_entropy
            orow[EC + E + e]     = sh_mx1[e];                // expert_confidence
            orow[EC + 2 * E + e] = sh_mx1[e] - sh_mx2[e];    // expert_margin
            sum_pl += pl;
            wsum = fmaf(pl, (float)(E - 1 - e), wsum);
            args[e] = sh_ix1[e];
        }

        // disagreement: sort 8 argmax indices, count unique
        for (int i = 1; i < E; i++) {
            int key = args[i]; int j = i - 1;
            while (j >= 0 && args[j] > key) { args[j + 1] = args[j]; j--; }
            args[j + 1] = key;
        }
        int nuniq = 1;
        for (int i = 1; i < E; i++) nuniq += (args[i] != args[i - 1]) ? 1 : 0;

        const int n_pairs = E * (E - 1) / 2;
        orow[EC + 3 * E + 0] = (float)(nuniq - 1) / (float)(E - 1);  // disagreement_ratio
        orow[EC + 3 * E + 1] = (wsum - acc[8]) / (float)n_pairs;     // mean_pairwise_kl
        orow[EC + 3 * E + 2] = acc[9];                               // mixture_entropy
        orow[EC + 3 * E + 3] = acc[10] / (float)C;                   // post_var
        orow[EC + 3 * E + 4] = acc[9] + sum_pl / (float)E;           // mutual_info
    }
}

extern "C" void kernel_launch(void* const* d_in, const int* in_sizes, int n_in,
                              void* d_out, int out_size)
{
    const float* p = (const float*)d_in[0];
    float* out = (float*)d_out;
    const int B = in_sizes[0] / EC;    // 8192 for this problem's shapes
    gating_feats_kernel<<<B, NT>>>(p, out);
}

// round 9
// speedup vs baseline: 1.1819x; 1.0013x over previous
#include <cuda_runtime.h>
#include <cstdint>

// GatingFeatureExtractor: p[B, E=8, C=1000] fp32 -> feats[B, E*C + 3E + 5] fp32.
// Smem-staged (R3 skeleton), one CTA per batch row:
//   A: block-wide cp.async gmem row -> smem (32KB), single wait
//   D: shift-corrected aligned copy smem -> out FIRST (stores drain early)
//   B: warp w = expert w: top2/argmax (float4 LDS, no MUFU)
//   C: thread t<250 owns classes 4t..4t+3: plogp[8] + prefix-KL cross +
//      mixture entropy + variance (conflict-free LDS.128)
//   F: thread 0 finalizes the 29 stat columns.
// __launch_bounds__(256,6): 40 regs -> 6 CTAs/SM.

#define EPS_F 1e-8f

constexpr int E = 8;
constexpr int C = 1000;
constexpr int C4 = C / 4;                  // 250
constexpr int EC = E * C;                  // 8000
constexpr int OUTW = EC + 3 * E + 5;       // 8029
constexpr int NT = 256;
constexpr int NW = NT / 32;

__device__ __forceinline__ void cp_async16(uint32_t saddr, const void* gptr) {
    asm volatile("cp.async.cg.shared.global [%0], [%1], 16;\n" ::"r"(saddr), "l"(gptr));
}

__global__ __launch_bounds__(NT, 6)
void gating_feats_kernel(const float* __restrict__ pin, float* __restrict__ out)
{
    __shared__ __align__(16) float sp[EC + 4];     // +4 pad: Phase D overlap read
    __shared__ float sh_mx1[E], sh_mx2[E];
    __shared__ int   sh_ix1[E];
    __shared__ float sh_red[NW][11];               // plogp[8], cross, mixent, var

    const int b    = blockIdx.x;
    const int tid  = threadIdx.x;
    const int wid  = tid >> 5;
    const int lane = tid & 31;

    const float* __restrict__ pr = pin + (size_t)b * EC;
    float* __restrict__ orow = out + (size_t)b * OUTW;
    // (b*OUTW)%4 == b%4 since OUTW%4==1; dst float4 frame starts at h.
    const int h = (4 - (b & 3)) & 3;

    // ---------------- Phase A: stage row into smem via cp.async ----------------
    if (tid < C4) {                                 // 250 threads, 8 x 16B each
        uint32_t sbase = (uint32_t)__cvta_generic_to_shared(sp) + 16u * (uint32_t)tid;
#pragma unroll
        for (int e = 0; e < E; e++)
            cp_async16(sbase + (uint32_t)(e * C * 4), pr + e * C + 4 * tid);
    }
    asm volatile("cp.async.commit_group;\n" ::: "memory");
    asm volatile("cp.async.wait_group 0;\n" ::: "memory");
    __syncthreads();

    // ---- Phase D: copy smem -> out FIRST, shift-corrected aligned STG.128 ----
    {
        const float4* __restrict__ sp4 = reinterpret_cast<const float4*>(sp);
        if (h == 0) {
            float4* __restrict__ dst4 = reinterpret_cast<float4*>(orow);
#pragma unroll
            for (int k = 0; k < 8; k++) {
                int j = tid + NT * k;
                if (j < EC / 4) dst4[j] = sp4[j];
            }
        } else {
            const int nvec = (EC - h) >> 2;        // 1999
            float4* __restrict__ dst4 = reinterpret_cast<float4*>(orow + h);
#pragma unroll
            for (int k = 0; k < 8; k++) {
                int j = tid + NT * k;
                if (j < nvec) {
                    float4 v = sp4[j];
                    float4 w = sp4[j + 1];          // padded overlap read
                    float4 o;
                    if (h == 1)      { o.x = v.y; o.y = v.z; o.z = v.w; o.w = w.x; }
                    else if (h == 2) { o.x = v.z; o.y = v.w; o.z = w.x; o.w = w.y; }
                    else             { o.x = v.w; o.y = w.x; o.z = w.y; o.w = w.z; }
                    dst4[j] = o;
                }
            }
            if (tid < h)     orow[tid] = sp[tid];                          // head
            if (tid < 4 - h) orow[h + 4 * nvec + tid] = sp[h + 4 * nvec + tid]; // tail
        }
    }

    // -------- Phase B: per-expert top2/argmax (warp = expert), no MUFU --------
    {
        const float4* __restrict__ row4 = reinterpret_cast<const float4*>(sp + wid * C);
        float m1 = -1.f, m2 = -1.f;
        int i1 = 0;
#pragma unroll
        for (int k = 0; k < 8; k++) {
            int idx = lane + 32 * k;
            if (idx < C4) {
                float4 v = row4[idx];
                float vv[4] = {v.x, v.y, v.z, v.w};
#pragma unroll
                for (int i = 0; i < 4; i++) {
                    float f = vv[i];
                    if (f > m1) { m2 = m1; m1 = f; i1 = 4 * idx + i; }
                    else        { m2 = fmaxf(m2, f); }
                }
            }
        }
#pragma unroll
        for (int off = 16; off; off >>= 1) {
            float o1 = __shfl_xor_sync(0xffffffffu, m1, off);
            float o2 = __shfl_xor_sync(0xffffffffu, m2, off);
            int   oi = __shfl_xor_sync(0xffffffffu, i1, off);
            if (o1 > m1 || (o1 == m1 && oi < i1)) {
                m2 = fmaxf(m1, o2); m1 = o1; i1 = oi;
            } else {
                m2 = fmaxf(m2, o1);
            }
        }
        if (lane == 0) { sh_mx1[wid] = m1; sh_mx2[wid] = m2; sh_ix1[wid] = i1; }
    }

    // ---------------- Phase C: single-pass cross-expert + plogp ----------------
    {
        float plogp[E];
#pragma unroll
        for (int e = 0; e < E; e++) plogp[e] = 0.f;
        float s_cross = 0.f, s_mixent = 0.f, s_var = 0.f;

        if (tid < C4) {                             // thread owns classes 4t..4t+3
            float pre[4] = {0.f, 0.f, 0.f, 0.f};
            float ssq[4] = {0.f, 0.f, 0.f, 0.f};
#pragma unroll
            for (int e = 0; e < E; e++) {
                float4 v = reinterpret_cast<const float4*>(sp + e * C)[tid];
                float vv[4] = {v.x, v.y, v.z, v.w};
                float pe = 0.f;
#pragma unroll
                for (int i = 0; i < 4; i++) {
                    float f = vv[i];
                    float lg = __logf(f + EPS_F);
                    pe = fmaf(f, lg, pe);
                    s_cross = fmaf(lg, pre[i], s_cross);  // sum_{i<j} p_i * logp_j
                    pre[i] += f;
                    ssq[i] = fmaf(f, f, ssq[i]);
                }
                plogp[e] = pe;
            }
#pragma unroll
            for (int i = 0; i < 4; i++) {
                float m = pre[i] * (1.0f / E);      // pre[] = full expert sum
                s_mixent = fmaf(-m, __logf(m + EPS_F), s_mixent);
                s_var = fmaf(ssq[i] - (float)E * m * m, 1.0f / (float)(E - 1), s_var);
            }
        }
        float r[11];
#pragma unroll
        for (int e = 0; e < E; e++) r[e] = plogp[e];
        r[8] = s_cross; r[9] = s_mixent; r[10] = s_var;
#pragma unroll
        for (int off = 16; off; off >>= 1)
#pragma unroll
            for (int k = 0; k < 11; k++)
                r[k] += __shfl_xor_sync(0xffffffffu, r[k], off);
        if (lane == 0)
#pragma unroll
            for (int k = 0; k < 11; k++) sh_red[wid][k] = r[k];
    }

    __syncthreads();

    // ---------------- Finalize: 29 stat columns ----------------
    if (tid == 0) {
        float acc[11];
#pragma unroll
        for (int k = 0; k < 11; k++) acc[k] = 0.f;
        for (int w = 0; w < NW; w++)
#pragma unroll
            for (int k = 0; k < 11; k++) acc[k] += sh_red[w][k];

        float sum_pl = 0.f, wsum = 0.f;
        int args[E];
#pragma unroll
        for (int e = 0; e < E; e++) {
            float pl = acc[e];
            orow[EC + e]         = -pl;                      // expert_entropy
            orow[EC + E + e]     = sh_mx1[e];                // expert_confidence
            orow[EC + 2 * E + e] = sh_mx1[e] - sh_mx2[e];    // expert_margin
            sum_pl += pl;
            wsum = fmaf(pl, (float)(E - 1 - e), wsum);
            args[e] = sh_ix1[e];
        }

        // disagreement: sort 8 argmax indices, count unique
        for (int i = 1; i < E; i++) {
            int key = args[i]; int j = i - 1;
            while (j >= 0 && args[j] > key) { args[j + 1] = args[j]; j--; }
            args[j + 1] = key;
        }
        int nuniq = 1;
        for (int i = 1; i < E; i++) nuniq += (args[i] != args[i - 1]) ? 1 : 0;

        const int n_pairs = E * (E - 1) / 2;
        orow[EC + 3 * E + 0] = (float)(nuniq - 1) / (float)(E - 1);  // disagreement_ratio
        orow[EC + 3 * E + 1] = (wsum - acc[8]) / (float)n_pairs;     // mean_pairwise_kl
        orow[EC + 3 * E + 2] = acc[9];                               // mixture_entropy
        orow[EC + 3 * E + 3] = acc[10] / (float)C;                   // post_var
        orow[EC + 3 * E + 4] = acc[9] + sum_pl / (float)E;           // mutual_info
    }
}

extern "C" void kernel_launch(void* const* d_in, const int* in_sizes, int n_in,
                              void* d_out, int out_size)
{
    const float* p = (const float*)d_in[0];
    float* out = (float*)d_out;
    const int B = in_sizes[0] / EC;    // 8192 for this problem's shapes
    gating_feats_kernel<<<B, NT>>>(p, out);
}